// round 5
// baseline (speedup 1.0000x reference)
#include <cuda_runtime.h>
#include <cuda_bf16.h>

// Problem: Out[64, 524288] = A @ X, where
//   X[k][j]   = x_flat[k*524288 + j]   (x reshaped (64, -1))
//   Out[i][j] = out_flat[i*524288 + j]
//   A = inv(2*(M11 + M22 + R - R^T)) @ M21,  M = L@L^T + 1e-8*I (128x128)
//
// Stage 1a: compute B = 2*(M11+M22+R-R^T) (+4eps diag) and M21.  (64 blocks)
// Stage 1b: Gauss-Jordan with partial pivoting: solve B Y = M21, store Y^T. (1 block)
// Stage 2:  big GEMM with packed fp32x2 FMAs (FFMA2), 64x128 tiles. (4096 blocks)

#define NCOLS 524288
#define EPS4 4e-8f

__device__ float g_B[64 * 64];
__device__ float g_M21[64 * 64];
__device__ float g_At[64 * 64];   // g_At[k*64 + r] = A[r][k]

// ---------------------------------------------------------------------------
// packed f32x2 helpers (Blackwell FFMA2 path — only reachable via PTX)
// ---------------------------------------------------------------------------
__device__ __forceinline__ unsigned long long dupf(float v) {
    unsigned long long r;
    asm("mov.b64 %0, {%1, %1};" : "=l"(r) : "f"(v));
    return r;
}
__device__ __forceinline__ void fma2(unsigned long long& d,
                                     unsigned long long a,
                                     unsigned long long b) {
    asm("fma.rn.f32x2 %0, %1, %2, %0;" : "+l"(d) : "l"(a), "l"(b));
}
__device__ __forceinline__ float2 unpk(unsigned long long v) {
    float2 r;
    asm("mov.b64 {%0, %1}, %2;" : "=f"(r.x), "=f"(r.y) : "l"(v));
    return r;
}

// ---------------------------------------------------------------------------
// Stage 1a: B and M21.  Block i computes row i of both.
// B[i][j]   = 2*( sum_k L[i,k]L[j,k] + sum_k L[i+64,k]L[j+64,k] + R[i,j]-R[j,i] ) (+4eps if i==j)
// M21[i][j] = sum_k L[i,k] L[j+64,k]
// ---------------------------------------------------------------------------
__global__ void prep_kernel(const float* __restrict__ L, const float* __restrict__ R) {
    __shared__ float Li[128], Li64[128];
    int i = blockIdx.x;
    int t = threadIdx.x;            // 128 threads
    Li[t]   = L[i * 128 + t];
    Li64[t] = L[(i + 64) * 128 + t];
    __syncthreads();
    if (t < 64) {
        int j = t;
        float s1 = 0.f, s2 = 0.f, s3 = 0.f;
        #pragma unroll 4
        for (int k = 0; k < 128; k++) {
            float lj   = __ldg(&L[j * 128 + k]);
            float lj64 = __ldg(&L[(j + 64) * 128 + k]);
            s1 = fmaf(Li[k],   lj,   s1);
            s2 = fmaf(Li64[k], lj64, s2);
            s3 = fmaf(Li[k],   lj64, s3);
        }
        float b = 2.0f * (s1 + s2 + __ldg(&R[i * 64 + j]) - __ldg(&R[j * 64 + i]));
        if (i == j) b += EPS4;
        g_B[i * 64 + j]   = b;
        g_M21[i * 64 + j] = s3;
    }
}

// ---------------------------------------------------------------------------
// Stage 1b: Gauss-Jordan with partial pivoting on [B | M21] (64 x 128).
// No per-pivot row normalization; divide by the diagonal at the end.
// 256 threads: thread t handles row r = t&63, column chunk ch = t>>6 (32 cols).
// ---------------------------------------------------------------------------
__global__ void solve_kernel() {
    __shared__ float Aug[64][129];   // pad -> conflict-free column access
    __shared__ int   s_piv;
    int t  = threadIdx.x;            // 256 threads
    int r  = t & 63;
    int ch = t >> 6;                 // 0..3

    // load augmented matrix
    #pragma unroll
    for (int p = 0; p < 32; p++) {
        int lin = p * 256 + t;       // 0..8191
        int rr = lin >> 7, cc = lin & 127;
        Aug[rr][cc] = (cc < 64) ? g_B[rr * 64 + cc] : g_M21[rr * 64 + (cc - 64)];
    }
    __syncthreads();

    for (int p = 0; p < 64; p++) {
        // partial pivot search (serial scan by thread 0; 64 independent LDS)
        if (t == 0) {
            int best = p;
            float bv = fabsf(Aug[p][p]);
            #pragma unroll 8
            for (int rr = p + 1; rr < 64; rr++) {
                float v = fabsf(Aug[rr][p]);
                if (v > bv) { bv = v; best = rr; }
            }
            s_piv = best;
        }
        __syncthreads();
        int piv = s_piv;
        if (piv != p && t < 128) {
            float tmp = Aug[p][t];
            Aug[p][t] = Aug[piv][t];
            Aug[piv][t] = tmp;
        }
        __syncthreads();
        float f = (r == p) ? 0.0f : Aug[r][p] / Aug[p][p];
        __syncthreads();             // all factors read before column p is clobbered
        if (r != p) {
            #pragma unroll 8
            for (int cc = 0; cc < 32; cc++) {
                int c = ch * 32 + cc;
                Aug[r][c] = fmaf(-f, Aug[p][c], Aug[r][c]);
            }
        }
        __syncthreads();
    }

    // left block is now diagonal; Y[r][k] = Aug[r][64+k] / Aug[r][r].  Store A^T.
    #pragma unroll
    for (int p = 0; p < 16; p++) {
        int lin = p * 256 + t;       // 0..4095
        int rr = lin >> 6, k = lin & 63;
        g_At[k * 64 + rr] = Aug[rr][64 + k] / Aug[rr][rr];
    }
}

// ---------------------------------------------------------------------------
// Stage 2: Out = A @ X via packed f32x2 FMAs.
// Block tile: 64 rows x 128 cols. 256 threads; thread = 8 rows x 4 cols.
// Smem: Xs 64x128 (32KB) + As (A^T, 64x64, 16KB) = 48KB static.
// A-pairs come pre-packed from LDS.128 of A^T (rows adjacent) -> zero packs;
// x needs 4 dup-packs per k (ALU pipe, overlaps the FMA pipe).
// ---------------------------------------------------------------------------
__global__ void __launch_bounds__(256) gemm_kernel(const float* __restrict__ x,
                                                   float* __restrict__ out) {
    __shared__ float Xs[64][128];
    __shared__ float As[64][64];     // As[k][r] = A[r][k]

    int t  = threadIdx.x;
    int jb = blockIdx.x * 128;

    // load A^T (1024 float4 / 256 thr = 4 each)
    #pragma unroll
    for (int p = 0; p < 4; p++) {
        int idx = p * 256 + t;
        ((float4*)As)[idx] = ((const float4*)g_At)[idx];
    }
    // load X tile (2048 float4 / 256 thr = 8 each); row segments contiguous 512B
    #pragma unroll
    for (int p = 0; p < 8; p++) {
        int lin = p * 256 + t;       // float4 index
        int row = lin >> 5;          // 32 float4 per row
        int c4  = lin & 31;
        ((float4*)(&Xs[row][0]))[c4] =
            ((const float4*)(x + row * NCOLS + jb))[c4];
    }
    __syncthreads();

    int cg = t & 31, rg = t >> 5;    // 32 col-groups x 8 row-groups
    int c0 = cg * 4, r0 = rg * 8;

    unsigned long long acc[4][4];    // [row-pair][col], pair = rows (r0+2rp, r0+2rp+1)
    #pragma unroll
    for (int i = 0; i < 4; i++)
        #pragma unroll
        for (int c = 0; c < 4; c++) acc[i][c] = 0ULL;

    #pragma unroll 16
    for (int k = 0; k < 64; k++) {
        float4 xv = *(const float4*)(&Xs[k][c0]);
        ulonglong2 aA = *(const ulonglong2*)(&As[k][r0]);      // rows (r0,r0+1),(r0+2,r0+3)
        ulonglong2 aB = *(const ulonglong2*)(&As[k][r0 + 4]);  // rows (r0+4..r0+7)
        unsigned long long x0 = dupf(xv.x), x1 = dupf(xv.y);
        unsigned long long x2 = dupf(xv.z), x3 = dupf(xv.w);
        fma2(acc[0][0], aA.x, x0); fma2(acc[0][1], aA.x, x1);
        fma2(acc[0][2], aA.x, x2); fma2(acc[0][3], aA.x, x3);
        fma2(acc[1][0], aA.y, x0); fma2(acc[1][1], aA.y, x1);
        fma2(acc[1][2], aA.y, x2); fma2(acc[1][3], aA.y, x3);
        fma2(acc[2][0], aB.x, x0); fma2(acc[2][1], aB.x, x1);
        fma2(acc[2][2], aB.x, x2); fma2(acc[2][3], aB.x, x3);
        fma2(acc[3][0], aB.y, x0); fma2(acc[3][1], aB.y, x1);
        fma2(acc[3][2], aB.y, x2); fma2(acc[3][3], aB.y, x3);
    }

    // store: each row-pair -> two float4 rows, coalesced (512B/warp per row)
    #pragma unroll
    for (int rp = 0; rp < 4; rp++) {
        float2 v0 = unpk(acc[rp][0]), v1 = unpk(acc[rp][1]);
        float2 v2 = unpk(acc[rp][2]), v3 = unpk(acc[rp][3]);
        int row = r0 + rp * 2;
        *(float4*)(out + row * NCOLS + jb + c0)       = make_float4(v0.x, v1.x, v2.x, v3.x);
        *(float4*)(out + (row + 1) * NCOLS + jb + c0) = make_float4(v0.y, v1.y, v2.y, v3.y);
    }
}

// ---------------------------------------------------------------------------
extern "C" void kernel_launch(void* const* d_in, const int* in_sizes, int n_in,
                              void* d_out, int out_size) {
    const float* x = nullptr;
    const float* L = nullptr;
    const float* R = nullptr;
    for (int i = 0; i < n_in; i++) {
        if (in_sizes[i] == 33554432)      x = (const float*)d_in[i];
        else if (in_sizes[i] == 16384)    L = (const float*)d_in[i];
        else if (in_sizes[i] == 4096)     R = (const float*)d_in[i];
    }
    if (!x) x = (const float*)d_in[0];
    if (!L) L = (const float*)d_in[1];
    if (!R) R = (const float*)d_in[2];

    prep_kernel<<<64, 128>>>(L, R);
    solve_kernel<<<1, 256>>>();
    gemm_kernel<<<NCOLS / 128, 256>>>(x, (float*)d_out);
}

// round 13
// speedup vs baseline: 1.3217x; 1.3217x over previous
#include <cuda_runtime.h>
#include <cuda_bf16.h>

// Out[64, 524288] = A @ X   with  A = inv(2*(M11+M22+R-R^T)) @ M21,
// M = L@L^T + 1e-8 I (128x128), X = x viewed as [64, 524288] row-major.
//
// Stage 1: prep   — tiled Gram kernel, 16 blocks, smem-staged coalesced loads.
// Stage 2: solve  — unpivoted Gauss-Jordan, rows in registers, 1 sync/iter.
//                   (symmetric part of B = 2(L1L1^T + L2L2^T) is PD -> stable.)
// Stage 3: gemm   — packed fp32x2 FFMA2 GEMM, 64x128 tiles (unchanged from R5).

#define NCOLS 524288
#define EPS4 4e-8f

__device__ float g_B[64 * 64];
__device__ float g_M21[64 * 64];
__device__ float g_At[64 * 64];   // g_At[k*64 + r] = A[r][k]

// ---------------------------------------------------------------------------
// packed f32x2 helpers (Blackwell FFMA2 path — only reachable via PTX)
// ---------------------------------------------------------------------------
__device__ __forceinline__ unsigned long long dupf(float v) {
    unsigned long long r;
    asm("mov.b64 %0, {%1, %1};" : "=l"(r) : "f"(v));
    return r;
}
__device__ __forceinline__ void fma2(unsigned long long& d,
                                     unsigned long long a,
                                     unsigned long long b) {
    asm("fma.rn.f32x2 %0, %1, %2, %0;" : "+l"(d) : "l"(a), "l"(b));
}
__device__ __forceinline__ float2 unpk(unsigned long long v) {
    float2 r;
    asm("mov.b64 {%0, %1}, %2;" : "=f"(r.x), "=f"(r.y) : "l"(v));
    return r;
}

// ---------------------------------------------------------------------------
// Stage 1: prep. Grid 16 blocks (4x4 tiling of the 64x64 (i,j) space), 256 thr.
// Block (bi,bj) computes i in [16bi,16bi+16), j in [16bj,16bj+16).
// Stages rows {i, i+64} and {j, j+64} of L into smem with coalesced float4
// loads, then 128-length dot products from smem (row pad 132 -> <=2-way cfl).
// ---------------------------------------------------------------------------
__global__ void __launch_bounds__(256) prep_kernel(const float* __restrict__ L,
                                                   const float* __restrict__ R) {
    __shared__ float Li[32][132];   // rows 0..15 = i, 16..31 = i+64
    __shared__ float Lj[32][132];
    int t  = threadIdx.x;
    int bi = blockIdx.x >> 2, bj = blockIdx.x & 3;

    #pragma unroll
    for (int p = 0; p < 4; p++) {
        int lin = p * 256 + t;       // 0..1023 float4 slots per buffer
        int rr  = lin >> 5;          // 32 float4 per 128-float row
        int q   = lin & 31;
        int gi  = bi * 16 + (rr & 15) + ((rr & 16) ? 64 : 0);
        int gj  = bj * 16 + (rr & 15) + ((rr & 16) ? 64 : 0);
        *(float4*)(&Li[rr][q * 4]) = *(const float4*)(L + gi * 128 + q * 4);
        *(float4*)(&Lj[rr][q * 4]) = *(const float4*)(L + gj * 128 + q * 4);
    }
    __syncthreads();

    int ii = t >> 4, jj = t & 15;
    float s1 = 0.f, s2 = 0.f, s3 = 0.f;
    #pragma unroll
    for (int q = 0; q < 32; q++) {
        float4 a  = *(const float4*)(&Li[ii][q * 4]);
        float4 a6 = *(const float4*)(&Li[ii + 16][q * 4]);
        float4 b  = *(const float4*)(&Lj[jj][q * 4]);
        float4 b6 = *(const float4*)(&Lj[jj + 16][q * 4]);
        s1 = fmaf(a.x,  b.x,  s1); s1 = fmaf(a.y,  b.y,  s1);
        s1 = fmaf(a.z,  b.z,  s1); s1 = fmaf(a.w,  b.w,  s1);
        s2 = fmaf(a6.x, b6.x, s2); s2 = fmaf(a6.y, b6.y, s2);
        s2 = fmaf(a6.z, b6.z, s2); s2 = fmaf(a6.w, b6.w, s2);
        s3 = fmaf(a.x,  b6.x, s3); s3 = fmaf(a.y,  b6.y, s3);
        s3 = fmaf(a.z,  b6.z, s3); s3 = fmaf(a.w,  b6.w, s3);
    }

    int i = bi * 16 + ii, j = bj * 16 + jj;
    float bv = 2.0f * (s1 + s2 + __ldg(&R[i * 64 + j]) - __ldg(&R[j * 64 + i]));
    if (i == j) bv += EPS4;
    g_B[i * 64 + j]   = bv;
    g_M21[i * 64 + j] = s3;
}

// ---------------------------------------------------------------------------
// Stage 2: solve. 1 block, 512 threads. Unpivoted Gauss-Jordan on [B | M21].
// Thread t owns row r = t>>3, 16 cols starting at (t&7)*16 — kept in REGISTERS.
// Pivot row double-buffered in smem -> exactly one __syncthreads per pivot.
// f broadcast to the 8 row-threads (warp-contiguous) via __shfl_sync.
// Pivot loop FULLY unrolled so row[p&15] is a static register index (no spills).
// ---------------------------------------------------------------------------
__global__ void __launch_bounds__(512) solve_kernel() {
    __shared__ float prow[2][128];
    __shared__ float sdiag[64];
    int t  = threadIdx.x;
    int r  = t >> 3;           // 0..63
    int cb = t & 7;            // 0..7
    int c0 = cb * 16;
    int rlane = (r & 3) * 8;   // base lane of this row inside its warp

    float row[16];
    #pragma unroll
    for (int q = 0; q < 16; q++) {
        int c = c0 + q;
        row[q] = (c < 64) ? g_B[r * 64 + c] : g_M21[r * 64 + (c - 64)];
    }

    #pragma unroll
    for (int p = 0; p < 64; p++) {
        int buf = p & 1;
        if (r == p) {
            #pragma unroll
            for (int q = 0; q < 16; q++) prow[buf][c0 + q] = row[q];
        }
        // my row's current value in column p (only valid on the owner lane)
        float vp = row[p & 15];                      // static index (full unroll)
        float fn = __shfl_sync(0xffffffffu, vp, rlane + (p >> 4));
        __syncthreads();
        if (r != p) {
            float f = fn / prow[buf][p];
            #pragma unroll
            for (int q = 0; q < 16; q++)
                row[q] = fmaf(-f, prow[buf][c0 + q], row[q]);
        }
    }

    // gather diagonal (left block is now diagonal), then write A^T
    #pragma unroll
    for (int q = 0; q < 16; q++)
        if (c0 + q == r) sdiag[r] = row[q];
    __syncthreads();
    if (c0 >= 64) {
        float dinv = 1.0f / sdiag[r];
        #pragma unroll
        for (int q = 0; q < 16; q++) {
            int k = c0 + q - 64;
            g_At[k * 64 + r] = row[q] * dinv;
        }
    }
}

// ---------------------------------------------------------------------------
// Stage 3: Out = A @ X via packed f32x2 FMAs (unchanged from R5 baseline).
// Block tile 64x128, 256 threads; thread = 8 rows x 4 cols; 48KB static smem.
// ---------------------------------------------------------------------------
__global__ void __launch_bounds__(256) gemm_kernel(const float* __restrict__ x,
                                                   float* __restrict__ out) {
    __shared__ float Xs[64][128];
    __shared__ float As[64][64];     // As[k][r] = A[r][k]

    int t  = threadIdx.x;
    int jb = blockIdx.x * 128;

    #pragma unroll
    for (int p = 0; p < 4; p++) {
        int idx = p * 256 + t;
        ((float4*)As)[idx] = ((const float4*)g_At)[idx];
    }
    #pragma unroll
    for (int p = 0; p < 8; p++) {
        int lin = p * 256 + t;
        int row = lin >> 5;
        int c4  = lin & 31;
        ((float4*)(&Xs[row][0]))[c4] =
            ((const float4*)(x + row * NCOLS + jb))[c4];
    }
    __syncthreads();

    int cg = t & 31, rg = t >> 5;
    int c0 = cg * 4, r0 = rg * 8;

    unsigned long long acc[4][4];
    #pragma unroll
    for (int i = 0; i < 4; i++)
        #pragma unroll
        for (int c = 0; c < 4; c++) acc[i][c] = 0ULL;

    #pragma unroll 16
    for (int k = 0; k < 64; k++) {
        float4 xv = *(const float4*)(&Xs[k][c0]);
        ulonglong2 aA = *(const ulonglong2*)(&As[k][r0]);
        ulonglong2 aB = *(const ulonglong2*)(&As[k][r0 + 4]);
        unsigned long long x0 = dupf(xv.x), x1 = dupf(xv.y);
        unsigned long long x2 = dupf(xv.z), x3 = dupf(xv.w);
        fma2(acc[0][0], aA.x, x0); fma2(acc[0][1], aA.x, x1);
        fma2(acc[0][2], aA.x, x2); fma2(acc[0][3], aA.x, x3);
        fma2(acc[1][0], aA.y, x0); fma2(acc[1][1], aA.y, x1);
        fma2(acc[1][2], aA.y, x2); fma2(acc[1][3], aA.y, x3);
        fma2(acc[2][0], aB.x, x0); fma2(acc[2][1], aB.x, x1);
        fma2(acc[2][2], aB.x, x2); fma2(acc[2][3], aB.x, x3);
        fma2(acc[3][0], aB.y, x0); fma2(acc[3][1], aB.y, x1);
        fma2(acc[3][2], aB.y, x2); fma2(acc[3][3], aB.y, x3);
    }

    #pragma unroll
    for (int rp = 0; rp < 4; rp++) {
        float2 v0 = unpk(acc[rp][0]), v1 = unpk(acc[rp][1]);
        float2 v2 = unpk(acc[rp][2]), v3 = unpk(acc[rp][3]);
        int row = r0 + rp * 2;
        *(float4*)(out + row * NCOLS + jb + c0)       = make_float4(v0.x, v1.x, v2.x, v3.x);
        *(float4*)(out + (row + 1) * NCOLS + jb + c0) = make_float4(v0.y, v1.y, v2.y, v3.y);
    }
}

// ---------------------------------------------------------------------------
extern "C" void kernel_launch(void* const* d_in, const int* in_sizes, int n_in,
                              void* d_out, int out_size) {
    const float* x = nullptr;
    const float* L = nullptr;
    const float* R = nullptr;
    for (int i = 0; i < n_in; i++) {
        if (in_sizes[i] == 33554432)      x = (const float*)d_in[i];
        else if (in_sizes[i] == 16384)    L = (const float*)d_in[i];
        else if (in_sizes[i] == 4096)     R = (const float*)d_in[i];
    }
    if (!x) x = (const float*)d_in[0];
    if (!L) L = (const float*)d_in[1];
    if (!R) R = (const float*)d_in[2];

    prep_kernel<<<16, 256>>>(L, R);
    solve_kernel<<<1, 512>>>();
    gemm_kernel<<<NCOLS / 128, 256>>>(x, (float*)d_out);
}